// round 5
// baseline (speedup 1.0000x reference)
#include <cuda_runtime.h>
#include <cstdint>

#define B_SZ 4
#define D_SZ 32
#define N_SZ 4096
#define BM 128
#define TN 128
#define NTILES (N_SZ / TN)
#define THREADS 256
#define YS 132                 // stride (floats) of [d][*] tiles
#define KTS 68                 // stride of per-warp Kt scratch

__device__ float g_ping[B_SZ * D_SZ * N_SZ];
__device__ float g_pong[B_SZ * D_SZ * N_SZ];

// smem float offsets
#define OFF_YM 0                            // [32][132]
#define OFF_YN (D_SZ * YS)                  // 4224: 2 x [32][132]
#define OFF_KT (OFF_YN + 2 * D_SZ * YS)     // 12672: 8 warps x [32][68]
#define OFF_SS (OFF_KT + 8 * 32 * KTS)      // 30080: [2][128]
#define SMEM_FLOATS (OFF_SS + 256)          // 30336
#define SMEM_BYTES (SMEM_FLOATS * 4)        // 121344

static __device__ __forceinline__ uint32_t to_tf32(float f) {
    uint32_t r; asm("cvt.rna.tf32.f32 %0, %1;" : "=r"(r) : "f"(f)); return r;
}
static __device__ __forceinline__ float ex2a(float x) {
    float r; asm("ex2.approx.f32 %0, %1;" : "=f"(r) : "f"(x)); return r;
}
static __device__ __forceinline__ void mma8(float* c, const uint32_t* a,
                                            uint32_t b0, uint32_t b1) {
    asm("mma.sync.aligned.m16n8k8.row.col.f32.tf32.tf32.f32 "
        "{%0,%1,%2,%3},{%4,%5,%6,%7},{%8,%9},{%0,%1,%2,%3};"
        : "+f"(c[0]), "+f"(c[1]), "+f"(c[2]), "+f"(c[3])
        : "r"(a[0]), "r"(a[1]), "r"(a[2]), "r"(a[3]), "r"(b0), "r"(b1));
}

// One mean-shift iteration. Warp (wm,wn) owns Kt rows [wm*32,+32) x cols [wn*64,+64):
// it produces that Kt block (MMA1+exp) and consumes it (MMA2 k-slice) -> warp-private,
// only 1 CTA-wide sync per tile (yn double-buffer publish).
__global__ __launch_bounds__(THREADS) void ms_iter_mma(const float* __restrict__ xin,
                                                       float* __restrict__ xout,
                                                       int mode) {
    extern __shared__ float sm[];
    float* ym  = sm + OFF_YM;
    float* ynb = sm + OFF_YN;
    float* sst = sm + OFF_SS;

    const float* gin  = (mode == 0) ? xin    : (mode == 1 ? g_ping : g_pong);
    float*       gout = (mode == 0) ? g_ping : (mode == 1 ? g_pong : xout);
    const int b  = blockIdx.y;
    const int m0 = blockIdx.x * BM;
    const float* Y = gin  + b * (D_SZ * N_SZ);
    float*       O = gout + b * (D_SZ * N_SZ);

    const int t    = threadIdx.x;
    const int wid  = t >> 5;
    const int lane = t & 31;
    const int g    = lane >> 2;
    const int k4   = lane & 3;
    const int wm   = wid & 3;          // m-group: 32 rows
    const int wn   = wid >> 2;         // n-half: 64 cols
    const int mr   = wm * 32;          // warp's first m-row
    const int nc0  = wn * 64;          // warp's first n-col
    float* kts = sm + OFF_KT + wid * (32 * KTS);   // warp-private Kt scratch

    const int pd = (t + 0) >> 5;       // staging ids (per r below: v = t + r*256)
    // ---- stage Ym (tf32) [d][m], and yn buf0 ----
    #pragma unroll
    for (int r = 0; r < 4; r++) {
        int v = t + r * THREADS;
        int d = v >> 5, j = (v & 31) * 4;
        float4 x = *(const float4*)&Y[d * N_SZ + m0 + j];
        uint4 u;
        u.x = to_tf32(x.x); u.y = to_tf32(x.y); u.z = to_tf32(x.z); u.w = to_tf32(x.w);
        *(uint4*)&ym[d * YS + j] = u;
        float4 x2 = *(const float4*)&Y[d * N_SZ + 0 + j];
        uint4 u2;
        u2.x = to_tf32(x2.x); u2.y = to_tf32(x2.y); u2.z = to_tf32(x2.z); u2.w = to_tf32(x2.w);
        *(uint4*)&ynb[d * YS + j] = u2;
    }
    (void)pd;
    __syncthreads();

    // ---- hoist A1 frags (warp's 32 Ym rows, all k) ----
    uint32_t a1[2][4][4];
    #pragma unroll
    for (int mi = 0; mi < 2; mi++)
        #pragma unroll
        for (int kc = 0; kc < 4; kc++) {
            int row = mr + mi * 16 + g;
            int d   = kc * 8 + k4;
            a1[mi][kc][0] = __float_as_uint(ym[d * YS + row]);
            a1[mi][kc][1] = __float_as_uint(ym[d * YS + row + 8]);
            a1[mi][kc][2] = __float_as_uint(ym[(d + 4) * YS + row]);
            a1[mi][kc][3] = __float_as_uint(ym[(d + 4) * YS + row + 8]);
        }

    float z[2][4][4];
    #pragma unroll
    for (int i = 0; i < 2; i++)
        #pragma unroll
        for (int j = 0; j < 4; j++)
            #pragma unroll
            for (int q = 0; q < 4; q++) z[i][j][q] = 0.0f;
    float Sp[2][2] = {{0.0f, 0.0f}, {0.0f, 0.0f}};
    const float C1 = 0.14426950408889634f;   // 0.1 * log2(e)

    for (int nt = 0; nt < NTILES; nt++) {
        float* cur = ynb + (nt & 1) * (D_SZ * YS);
        // ---- prefetch next yn tile into regs ----
        float4 p[4];
        if (nt < NTILES - 1) {
            #pragma unroll
            for (int r = 0; r < 4; r++) {
                int v = t + r * THREADS;
                int d = v >> 5, j = (v & 31) * 4;
                p[r] = *(const float4*)&Y[d * N_SZ + (nt + 1) * TN + j];
            }
        }

        // ---- fused per-ni: MMA1 -> exp -> Kt -> MMA2(kc=ni) ----
        #pragma unroll
        for (int ni = 0; ni < 8; ni++) {
            const int ncol = nc0 + ni * 8 + g;
            float c[2][4];
            #pragma unroll
            for (int mi = 0; mi < 2; mi++)
                #pragma unroll
                for (int q = 0; q < 4; q++) c[mi][q] = 0.0f;
            #pragma unroll
            for (int kc = 0; kc < 4; kc++) {
                uint32_t b0 = __float_as_uint(cur[(kc * 8 + k4) * YS + ncol]);
                uint32_t b1 = __float_as_uint(cur[(kc * 8 + k4 + 4) * YS + ncol]);
                mma8(c[0], a1[0][kc], b0, b1);
                mma8(c[1], a1[1][kc], b0, b1);
            }
            #pragma unroll
            for (int mi = 0; mi < 2; mi++) {
                float e0 = ex2a(c[mi][0] * C1);
                float e1 = ex2a(c[mi][1] * C1);
                float e2 = ex2a(c[mi][2] * C1);
                float e3 = ex2a(c[mi][3] * C1);
                Sp[mi][0] += e0 + e1;
                Sp[mi][1] += e2 + e3;
                float2 lo, hi;
                lo.x = __uint_as_float(to_tf32(e0)); lo.y = __uint_as_float(to_tf32(e1));
                hi.x = __uint_as_float(to_tf32(e2)); hi.y = __uint_as_float(to_tf32(e3));
                int rl = mi * 16 + g;
                *(float2*)&kts[rl * KTS + ni * 8 + 2 * k4]       = lo;
                *(float2*)&kts[(rl + 8) * KTS + ni * 8 + 2 * k4] = hi;
            }
            __syncwarp();
            // MMA2 k-chunk = this ni's 8 n-cols
            uint32_t a2[2][4];
            #pragma unroll
            for (int mi = 0; mi < 2; mi++) {
                int rl = mi * 16 + g;
                a2[mi][0] = __float_as_uint(kts[rl * KTS + ni * 8 + k4]);
                a2[mi][1] = __float_as_uint(kts[(rl + 8) * KTS + ni * 8 + k4]);
                a2[mi][2] = __float_as_uint(kts[rl * KTS + ni * 8 + k4 + 4]);
                a2[mi][3] = __float_as_uint(kts[(rl + 8) * KTS + ni * 8 + k4 + 4]);
            }
            #pragma unroll
            for (int di = 0; di < 4; di++) {
                uint32_t b0 = __float_as_uint(cur[(di * 8 + g) * YS + nc0 + ni * 8 + k4]);
                uint32_t b1 = __float_as_uint(cur[(di * 8 + g) * YS + nc0 + ni * 8 + k4 + 4]);
                mma8(z[0][di], a2[0], b0, b1);
                mma8(z[1][di], a2[1], b0, b1);
            }
        }

        // ---- publish next yn buffer ----
        if (nt < NTILES - 1) {
            float* nb = ynb + ((nt + 1) & 1) * (D_SZ * YS);
            #pragma unroll
            for (int r = 0; r < 4; r++) {
                int v = t + r * THREADS;
                int d = v >> 5, j = (v & 31) * 4;
                uint4 u;
                u.x = to_tf32(p[r].x); u.y = to_tf32(p[r].y);
                u.z = to_tf32(p[r].z); u.w = to_tf32(p[r].w);
                *(uint4*)&nb[d * YS + j] = u;
            }
        }
        __syncthreads();
    }

    // ---- S quad-reduce (over k4) ----
    #pragma unroll
    for (int mi = 0; mi < 2; mi++)
        #pragma unroll
        for (int h = 0; h < 2; h++) {
            Sp[mi][h] += __shfl_xor_sync(0xFFFFFFFFu, Sp[mi][h], 1);
            Sp[mi][h] += __shfl_xor_sync(0xFFFFFFFFu, Sp[mi][h], 2);
        }
    __syncthreads();                       // all kt reads done -> safe to alias as zst

    float* zst = sm + OFF_KT;              // [2 wn][128 m][32 d]
    if (k4 == 0) {
        #pragma unroll
        for (int mi = 0; mi < 2; mi++) {
            sst[wn * 128 + mr + mi * 16 + g]     = Sp[mi][0];
            sst[wn * 128 + mr + mi * 16 + g + 8] = Sp[mi][1];
        }
    }
    #pragma unroll
    for (int mi = 0; mi < 2; mi++)
        #pragma unroll
        for (int di = 0; di < 4; di++) {
            int row = mr + mi * 16 + g;
            int d   = di * 8 + 2 * k4;
            zst[wn * 4096 + row * 32 + d]           = z[mi][di][0];
            zst[wn * 4096 + row * 32 + d + 1]       = z[mi][di][1];
            zst[wn * 4096 + (row + 8) * 32 + d]     = z[mi][di][2];
            zst[wn * 4096 + (row + 8) * 32 + d + 1] = z[mi][di][3];
        }
    __syncthreads();

    // ---- final: sum wn halves, normalize, blend, store ----
    {
        const int m  = t & 127;
        const int d0 = (t >> 7) * 16;
        float Ssum = sst[m] + sst[128 + m];
        float inv = 0.5f / Ssum;
        #pragma unroll
        for (int dd = 0; dd < 16; dd++) {
            int d = d0 + dd;
            float zz = zst[m * 32 + d] + zst[4096 + m * 32 + d];
            O[d * N_SZ + m0 + m] = zz * inv + 0.5f * Y[d * N_SZ + m0 + m];
        }
    }
}

extern "C" void kernel_launch(void* const* d_in, const int* in_sizes, int n_in,
                              void* d_out, int out_size) {
    const float* x = (const float*)d_in[0];
    float* out = (float*)d_out;
    cudaFuncSetAttribute(ms_iter_mma, cudaFuncAttributeMaxDynamicSharedMemorySize,
                         SMEM_BYTES);
    dim3 grid(N_SZ / BM, B_SZ);
    ms_iter_mma<<<grid, THREADS, SMEM_BYTES>>>(x, out, 0);   // x      -> g_ping
    ms_iter_mma<<<grid, THREADS, SMEM_BYTES>>>(x, out, 1);   // g_ping -> g_pong
    ms_iter_mma<<<grid, THREADS, SMEM_BYTES>>>(x, out, 2);   // g_pong -> out
}

// round 6
// speedup vs baseline: 1.1231x; 1.1231x over previous
#include <cuda_runtime.h>
#include <cstdint>

#define B_SZ 4
#define D_SZ 32
#define N_SZ 4096
#define BM 64                  // m-cols per CTA (halved for 2 CTAs/SM)
#define TN 128
#define NTILES (N_SZ / TN)
#define THREADS 256
#define YS 132                 // stride (floats) of [d][*] yn tiles
#define YMS 68                 // stride of ym tile
#define KTS 36                 // stride of per-warp Kt scratch (32x32)

__device__ float g_ping[B_SZ * D_SZ * N_SZ];
__device__ float g_pong[B_SZ * D_SZ * N_SZ];

// smem float offsets
#define OFF_YM 0                            // [32][68]   = 2176
#define OFF_YN (D_SZ * YMS)                 // 2176: 2 x [32][132] = 8448
#define OFF_KT (OFF_YN + 2 * D_SZ * YS)     // 10624: 8 warps x [32][36] = 9216
#define OFF_SS (OFF_KT + 8 * 32 * KTS)      // 19840: [4][64]
#define SMEM_FLOATS (OFF_SS + 256)          // 20096
#define SMEM_BYTES (SMEM_FLOATS * 4)        // 80384

static __device__ __forceinline__ uint32_t to_tf32(float f) {
    uint32_t r; asm("cvt.rna.tf32.f32 %0, %1;" : "=r"(r) : "f"(f)); return r;
}
static __device__ __forceinline__ float ex2a(float x) {
    float r; asm("ex2.approx.f32 %0, %1;" : "=f"(r) : "f"(x)); return r;
}
static __device__ __forceinline__ void mma8(float* c, const uint32_t* a,
                                            uint32_t b0, uint32_t b1) {
    asm("mma.sync.aligned.m16n8k8.row.col.f32.tf32.tf32.f32 "
        "{%0,%1,%2,%3},{%4,%5,%6,%7},{%8,%9},{%0,%1,%2,%3};"
        : "+f"(c[0]), "+f"(c[1]), "+f"(c[2]), "+f"(c[3])
        : "r"(a[0]), "r"(a[1]), "r"(a[2]), "r"(a[3]), "r"(b0), "r"(b1));
}

// One mean-shift iteration. CTA owns 64 m-cols. Warp (wm,wn) owns Kt rows
// [wm*32,+32) x cols [wn*32,+32) of each 128-n tile: produces it (MMA1+exp)
// and consumes it (MMA2 k-slice) warp-privately.
__global__ __launch_bounds__(THREADS, 2)
void ms_iter_mma(const float* __restrict__ xin, float* __restrict__ xout, int mode) {
    extern __shared__ float sm[];
    float* ym  = sm + OFF_YM;
    float* ynb = sm + OFF_YN;
    float* sst = sm + OFF_SS;

    const float* gin  = (mode == 0) ? xin    : (mode == 1 ? g_ping : g_pong);
    float*       gout = (mode == 0) ? g_ping : (mode == 1 ? g_pong : xout);
    const int b  = blockIdx.y;
    const int m0 = blockIdx.x * BM;
    const float* Y = gin  + b * (D_SZ * N_SZ);
    float*       O = gout + b * (D_SZ * N_SZ);

    const int t    = threadIdx.x;
    const int wid  = t >> 5;
    const int lane = t & 31;
    const int g    = lane >> 2;
    const int k4   = lane & 3;
    const int wm   = wid & 1;          // m-group: 32 rows
    const int wn   = wid >> 1;         // n-quarter: 32 cols
    const int mr   = wm * 32;
    const int nc0  = wn * 32;
    float* kts = sm + OFF_KT + wid * (32 * KTS);

    // ---- stage Ym (tf32) [d][m] and yn buf0 ----
    #pragma unroll
    for (int r = 0; r < 2; r++) {
        int v = t + r * THREADS;                 // 512 float4 = 64x32
        int d = v >> 4, j = (v & 15) * 4;
        float4 x = *(const float4*)&Y[d * N_SZ + m0 + j];
        uint4 u;
        u.x = to_tf32(x.x); u.y = to_tf32(x.y); u.z = to_tf32(x.z); u.w = to_tf32(x.w);
        *(uint4*)&ym[d * YMS + j] = u;
    }
    #pragma unroll
    for (int r = 0; r < 4; r++) {
        int v = t + r * THREADS;                 // 1024 float4 = 128x32
        int d = v >> 5, j = (v & 31) * 4;
        float4 x = *(const float4*)&Y[d * N_SZ + j];
        uint4 u;
        u.x = to_tf32(x.x); u.y = to_tf32(x.y); u.z = to_tf32(x.z); u.w = to_tf32(x.w);
        *(uint4*)&ynb[d * YS + j] = u;
    }
    __syncthreads();

    // ---- hoist A1 frags (warp's 32 Ym rows, all 4 k-chunks) ----
    uint32_t a1[2][4][4];
    #pragma unroll
    for (int mi = 0; mi < 2; mi++)
        #pragma unroll
        for (int kc = 0; kc < 4; kc++) {
            int row = mr + mi * 16 + g;
            int d   = kc * 8 + k4;
            a1[mi][kc][0] = __float_as_uint(ym[d * YMS + row]);
            a1[mi][kc][1] = __float_as_uint(ym[d * YMS + row + 8]);
            a1[mi][kc][2] = __float_as_uint(ym[(d + 4) * YMS + row]);
            a1[mi][kc][3] = __float_as_uint(ym[(d + 4) * YMS + row + 8]);
        }

    float z[2][4][4];
    #pragma unroll
    for (int i = 0; i < 2; i++)
        #pragma unroll
        for (int j = 0; j < 4; j++)
            #pragma unroll
            for (int q = 0; q < 4; q++) z[i][j][q] = 0.0f;
    float Sp[2][2] = {{0.0f, 0.0f}, {0.0f, 0.0f}};
    const float C1 = 0.14426950408889634f;   // 0.1 * log2(e)

    for (int nt = 0; nt < NTILES; nt++) {
        float* cur = ynb + (nt & 1) * (D_SZ * YS);
        // ---- prefetch next yn tile into regs ----
        float4 p[4];
        if (nt < NTILES - 1) {
            #pragma unroll
            for (int r = 0; r < 4; r++) {
                int v = t + r * THREADS;
                int d = v >> 5, j = (v & 31) * 4;
                p[r] = *(const float4*)&Y[d * N_SZ + (nt + 1) * TN + j];
            }
        }

        // ---- fused per-ni (4 x 8 cols): MMA1 -> exp -> Kt -> MMA2 ----
        #pragma unroll
        for (int ni = 0; ni < 4; ni++) {
            const int ncol = nc0 + ni * 8 + g;
            float c[2][4];
            #pragma unroll
            for (int mi = 0; mi < 2; mi++)
                #pragma unroll
                for (int q = 0; q < 4; q++) c[mi][q] = 0.0f;
            #pragma unroll
            for (int kc = 0; kc < 4; kc++) {
                uint32_t b0 = __float_as_uint(cur[(kc * 8 + k4) * YS + ncol]);
                uint32_t b1 = __float_as_uint(cur[(kc * 8 + k4 + 4) * YS + ncol]);
                mma8(c[0], a1[0][kc], b0, b1);
                mma8(c[1], a1[1][kc], b0, b1);
            }
            #pragma unroll
            for (int mi = 0; mi < 2; mi++) {
                float e0 = ex2a(c[mi][0] * C1);
                float e1 = ex2a(c[mi][1] * C1);
                float e2 = ex2a(c[mi][2] * C1);
                float e3 = ex2a(c[mi][3] * C1);
                Sp[mi][0] += e0 + e1;
                Sp[mi][1] += e2 + e3;
                float2 lo, hi;
                lo.x = __uint_as_float(to_tf32(e0)); lo.y = __uint_as_float(to_tf32(e1));
                hi.x = __uint_as_float(to_tf32(e2)); hi.y = __uint_as_float(to_tf32(e3));
                int rl = mi * 16 + g;
                *(float2*)&kts[rl * KTS + ni * 8 + 2 * k4]       = lo;
                *(float2*)&kts[(rl + 8) * KTS + ni * 8 + 2 * k4] = hi;
            }
            __syncwarp();
            // MMA2 k-chunk = this ni's 8 n-cols
            uint32_t a2[2][4];
            #pragma unroll
            for (int mi = 0; mi < 2; mi++) {
                int rl = mi * 16 + g;
                a2[mi][0] = __float_as_uint(kts[rl * KTS + ni * 8 + k4]);
                a2[mi][1] = __float_as_uint(kts[(rl + 8) * KTS + ni * 8 + k4]);
                a2[mi][2] = __float_as_uint(kts[rl * KTS + ni * 8 + k4 + 4]);
                a2[mi][3] = __float_as_uint(kts[(rl + 8) * KTS + ni * 8 + k4 + 4]);
            }
            #pragma unroll
            for (int di = 0; di < 4; di++) {
                uint32_t b0 = __float_as_uint(cur[(di * 8 + g) * YS + nc0 + ni * 8 + k4]);
                uint32_t b1 = __float_as_uint(cur[(di * 8 + g) * YS + nc0 + ni * 8 + k4 + 4]);
                mma8(z[0][di], a2[0], b0, b1);
                mma8(z[1][di], a2[1], b0, b1);
            }
        }

        // ---- publish next yn buffer ----
        if (nt < NTILES - 1) {
            float* nb = ynb + ((nt + 1) & 1) * (D_SZ * YS);
            #pragma unroll
            for (int r = 0; r < 4; r++) {
                int v = t + r * THREADS;
                int d = v >> 5, j = (v & 31) * 4;
                uint4 u;
                u.x = to_tf32(p[r].x); u.y = to_tf32(p[r].y);
                u.z = to_tf32(p[r].z); u.w = to_tf32(p[r].w);
                *(uint4*)&nb[d * YS + j] = u;
            }
        }
        __syncthreads();
    }

    // ---- S quad-reduce (over k4 lanes) ----
    #pragma unroll
    for (int mi = 0; mi < 2; mi++)
        #pragma unroll
        for (int h = 0; h < 2; h++) {
            Sp[mi][h] += __shfl_xor_sync(0xFFFFFFFFu, Sp[mi][h], 1);
            Sp[mi][h] += __shfl_xor_sync(0xFFFFFFFFu, Sp[mi][h], 2);
        }
    __syncthreads();                       // kt reads done -> alias as zst

    float* zst = sm + OFF_KT;              // [4 wn][64 m][32 d] = 32KB (fits in kt)
    if (k4 == 0) {
        #pragma unroll
        for (int mi = 0; mi < 2; mi++) {
            sst[wn * 64 + mr + mi * 16 + g]     = Sp[mi][0];
            sst[wn * 64 + mr + mi * 16 + g + 8] = Sp[mi][1];
        }
    }
    #pragma unroll
    for (int mi = 0; mi < 2; mi++)
        #pragma unroll
        for (int di = 0; di < 4; di++) {
            int row = mr + mi * 16 + g;
            int d   = di * 8 + 2 * k4;
            float2 lo, hi;
            lo.x = z[mi][di][0]; lo.y = z[mi][di][1];
            hi.x = z[mi][di][2]; hi.y = z[mi][di][3];
            *(float2*)&zst[wn * 2048 + row * 32 + d]       = lo;
            *(float2*)&zst[wn * 2048 + (row + 8) * 32 + d] = hi;
        }
    __syncthreads();

    // ---- final: sum 4 wn slices, normalize, blend, store ----
    {
        const int m  = t & 63;
        const int d0 = (t >> 6) * 8;
        float Ssum = sst[m] + sst[64 + m] + sst[128 + m] + sst[192 + m];
        float inv = 0.5f / Ssum;
        #pragma unroll
        for (int dd = 0; dd < 8; dd++) {
            int d = d0 + dd;
            float zz = zst[m * 32 + d] + zst[2048 + m * 32 + d] +
                       zst[4096 + m * 32 + d] + zst[6144 + m * 32 + d];
            O[d * N_SZ + m0 + m] = zz * inv + 0.5f * Y[d * N_SZ + m0 + m];
        }
    }
}

extern "C" void kernel_launch(void* const* d_in, const int* in_sizes, int n_in,
                              void* d_out, int out_size) {
    const float* x = (const float*)d_in[0];
    float* out = (float*)d_out;
    cudaFuncSetAttribute(ms_iter_mma, cudaFuncAttributeMaxDynamicSharedMemorySize,
                         SMEM_BYTES);
    dim3 grid(N_SZ / BM, B_SZ);
    ms_iter_mma<<<grid, THREADS, SMEM_BYTES>>>(x, out, 0);   // x      -> g_ping
    ms_iter_mma<<<grid, THREADS, SMEM_BYTES>>>(x, out, 1);   // g_ping -> g_pong
    ms_iter_mma<<<grid, THREADS, SMEM_BYTES>>>(x, out, 2);   // g_pong -> out
}

// round 8
// speedup vs baseline: 1.1835x; 1.0538x over previous
#include <cuda_runtime.h>
#include <cstdint>

#define B_SZ 4
#define D_SZ 32
#define N_SZ 4096
#define BM 64                  // m-cols per CTA (2 CTAs/SM)
#define TN 128
#define NTILES (N_SZ / TN)
#define THREADS 256
#define YMS 68                 // ym tile stride (floats)
#define YPS 264                // yp row stride in floats (128 float2 + 4 pad pairs)
#define KTS 36                 // Kt scratch stride

__device__ float g_ping[B_SZ * D_SZ * N_SZ];
__device__ float g_pong[B_SZ * D_SZ * N_SZ];

// smem float offsets
#define OFF_YM 0                            // [32][68] = 2176
#define OFF_YP 2176                         // 2 x [16][264] = 8448 (paired yn, dbuf)
#define OFF_KT 10624                        // 8 warps x [32][36] = 9216
#define OFF_SS 19840                        // [4][64]
#define SMEM_FLOATS 20096
#define SMEM_BYTES (SMEM_FLOATS * 4)        // 80384

static __device__ __forceinline__ uint32_t to_tf32(float f) {
    uint32_t r; asm("cvt.rna.tf32.f32 %0, %1;" : "=r"(r) : "f"(f)); return r;
}
static __device__ __forceinline__ float ex2a(float x) {
    float r; asm("ex2.approx.f32 %0, %1;" : "=f"(r) : "f"(x)); return r;
}
static __device__ __forceinline__ void mma8(float* c, const uint32_t* a,
                                            uint32_t b0, uint32_t b1) {
    asm("mma.sync.aligned.m16n8k8.row.col.f32.tf32.tf32.f32 "
        "{%0,%1,%2,%3},{%4,%5,%6,%7},{%8,%9},{%0,%1,%2,%3};"
        : "+f"(c[0]), "+f"(c[1]), "+f"(c[2]), "+f"(c[3])
        : "r"(a[0]), "r"(a[1]), "r"(a[2]), "r"(a[3]), "r"(b0), "r"(b1));
}

// One mean-shift iteration. CTA owns 64 m-cols; warp (wm,wn) owns Kt rows
// [wm*32,+32) x cols [wn*32,+32) per 128-n tile (produce + consume warp-private).
// yn is stored PAIRED: yp[4*(d>>3)+(d&3)][n] = (y[d][n], y[d+4][n]) so MMA1's
// (b0,b1) is one LDS.64 and all smem access patterns are bank-conflict-free.
__global__ __launch_bounds__(THREADS, 2)
void ms_iter_mma(const float* __restrict__ xin, float* __restrict__ xout, int mode) {
    extern __shared__ float sm[];
    float* ym  = sm + OFF_YM;
    float* ypb = sm + OFF_YP;
    float* sst = sm + OFF_SS;

    const float* gin  = (mode == 0) ? xin    : (mode == 1 ? g_ping : g_pong);
    float*       gout = (mode == 0) ? g_ping : (mode == 1 ? g_pong : xout);
    const int b  = blockIdx.y;
    const int m0 = blockIdx.x * BM;
    const float* Y = gin  + b * (D_SZ * N_SZ);
    float*       O = gout + b * (D_SZ * N_SZ);

    const int t    = threadIdx.x;
    const int wid  = t >> 5;
    const int lane = t & 31;
    const int g    = lane >> 2;
    const int k4   = lane & 3;
    const int wm   = wid & 1;
    const int wn   = wid >> 1;
    const int mr   = wm * 32;
    const int nc0  = wn * 32;
    float* kts = sm + OFF_KT + wid * (32 * KTS);

    // Kt column permutation psi(c) = c ^ (c >> 2) applied within 8-col chunks
    const int st0 = (2 * k4) ^ ((2 * k4) >> 2);            // store col of e0/e2
    const int st1 = (2 * k4 + 1) ^ ((2 * k4 + 1) >> 2);    // store col of e1/e3
    const int ld1 = (k4 + 4) ^ 1;                          // read col for logical k4+4

    // ---- stage Ym (tf32) [d][m] and yp buf0 ----
    #pragma unroll
    for (int r = 0; r < 2; r++) {
        int v = t + r * THREADS;                 // 512 float4 = 64x32
        int d = v >> 4, j = (v & 15) * 4;
        float4 x = *(const float4*)&Y[d * N_SZ + m0 + j];
        uint4 u;
        u.x = to_tf32(x.x); u.y = to_tf32(x.y); u.z = to_tf32(x.z); u.w = to_tf32(x.w);
        *(uint4*)&ym[d * YMS + j] = u;
    }
    #pragma unroll
    for (int it = 0; it < 4; it++) {
        int v = t + it * THREADS;
        int r = v >> 6, jj = (v & 63) * 2;       // pair-row r, n-cols jj, jj+1
        int dlo = 8 * (r >> 2) + (r & 3);
        float2 a = *(const float2*)&Y[dlo * N_SZ + jj];
        float2 c = *(const float2*)&Y[(dlo + 4) * N_SZ + jj];
        uint4 u;
        u.x = to_tf32(a.x); u.y = to_tf32(c.x);
        u.z = to_tf32(a.y); u.w = to_tf32(c.y);
        *(uint4*)&ypb[r * YPS + 2 * jj] = u;
    }
    __syncthreads();

    // ---- hoist A1 frags (warp's 32 Ym rows, all 4 k-chunks) ----
    uint32_t a1[2][4][4];
    #pragma unroll
    for (int mi = 0; mi < 2; mi++)
        #pragma unroll
        for (int kc = 0; kc < 4; kc++) {
            int row = mr + mi * 16 + g;
            int d   = kc * 8 + k4;
            a1[mi][kc][0] = __float_as_uint(ym[d * YMS + row]);
            a1[mi][kc][1] = __float_as_uint(ym[d * YMS + row + 8]);
            a1[mi][kc][2] = __float_as_uint(ym[(d + 4) * YMS + row]);
            a1[mi][kc][3] = __float_as_uint(ym[(d + 4) * YMS + row + 8]);
        }

    float z[2][4][4];
    #pragma unroll
    for (int i = 0; i < 2; i++)
        #pragma unroll
        for (int j = 0; j < 4; j++)
            #pragma unroll
            for (int q = 0; q < 4; q++) z[i][j][q] = 0.0f;
    float Sp[2][2] = {{0.0f, 0.0f}, {0.0f, 0.0f}};
    const float C1 = 0.14426950408889634f;   // 0.1 * log2(e)

    for (int nt = 0; nt < NTILES; nt++) {
        float* cur = ypb + (nt & 1) * (16 * YPS);
        // ---- prefetch next yn pair-tile into regs ----
        float2 pa[4], pc[4];
        if (nt < NTILES - 1) {
            const int n1 = (nt + 1) * TN;
            #pragma unroll
            for (int it = 0; it < 4; it++) {
                int v = t + it * THREADS;
                int r = v >> 6, jj = (v & 63) * 2;
                int dlo = 8 * (r >> 2) + (r & 3);
                pa[it] = *(const float2*)&Y[dlo * N_SZ + n1 + jj];
                pc[it] = *(const float2*)&Y[(dlo + 4) * N_SZ + n1 + jj];
            }
        }

        // ---- fused per-ni (4 x 8 cols): MMA1 -> exp -> Kt -> MMA2 ----
        #pragma unroll
        for (int ni = 0; ni < 4; ni++) {
            const int ncol = nc0 + ni * 8 + g;
            float c[2][4];
            #pragma unroll
            for (int mi = 0; mi < 2; mi++)
                #pragma unroll
                for (int q = 0; q < 4; q++) c[mi][q] = 0.0f;
            #pragma unroll
            for (int kc = 0; kc < 4; kc++) {
                // one LDS.64 gives (b0, b1) = y[8kc+k4][ncol], y[8kc+k4+4][ncol]
                float2 bv = *(const float2*)&cur[(4 * kc + k4) * YPS + 2 * ncol];
                uint32_t b0 = __float_as_uint(bv.x);
                uint32_t b1 = __float_as_uint(bv.y);
                mma8(c[0], a1[0][kc], b0, b1);
                mma8(c[1], a1[1][kc], b0, b1);
            }
            #pragma unroll
            for (int mi = 0; mi < 2; mi++) {
                float e0 = ex2a(c[mi][0] * C1);
                float e1 = ex2a(c[mi][1] * C1);
                float e2 = ex2a(c[mi][2] * C1);
                float e3 = ex2a(c[mi][3] * C1);
                Sp[mi][0] += e0 + e1;
                Sp[mi][1] += e2 + e3;
                int rl = mi * 16 + g;
                kts[rl * KTS + ni * 8 + st0]       = __uint_as_float(to_tf32(e0));
                kts[rl * KTS + ni * 8 + st1]       = __uint_as_float(to_tf32(e1));
                kts[(rl + 8) * KTS + ni * 8 + st0] = __uint_as_float(to_tf32(e2));
                kts[(rl + 8) * KTS + ni * 8 + st1] = __uint_as_float(to_tf32(e3));
            }
            __syncwarp();
            // MMA2 k-chunk = this ni's 8 n-cols (psi: col k4 -> k4, col k4+4 -> (k4+4)^1)
            uint32_t a2[2][4];
            #pragma unroll
            for (int mi = 0; mi < 2; mi++) {
                int rl = mi * 16 + g;
                a2[mi][0] = __float_as_uint(kts[rl * KTS + ni * 8 + k4]);
                a2[mi][1] = __float_as_uint(kts[(rl + 8) * KTS + ni * 8 + k4]);
                a2[mi][2] = __float_as_uint(kts[rl * KTS + ni * 8 + ld1]);
                a2[mi][3] = __float_as_uint(kts[(rl + 8) * KTS + ni * 8 + ld1]);
            }
            #pragma unroll
            for (int di = 0; di < 4; di++) {
                // MMA2 B: y[8di+g][n] = yp[4di+(g&3)][n], component (g>>2)
                int base = (4 * di + (g & 3)) * YPS + 2 * (nc0 + ni * 8 + k4) + (g >> 2);
                uint32_t b0 = __float_as_uint(cur[base]);
                uint32_t b1 = __float_as_uint(cur[base + 8]);   // n-col k4+4
                mma8(z[0][di], a2[0], b0, b1);
                mma8(z[1][di], a2[1], b0, b1);
            }
        }

        // ---- publish next yp buffer ----
        if (nt < NTILES - 1) {
            float* nb = ypb + ((nt + 1) & 1) * (16 * YPS);
            #pragma unroll
            for (int it = 0; it < 4; it++) {
                int v = t + it * THREADS;
                int r = v >> 6, jj = (v & 63) * 2;
                uint4 u;
                u.x = to_tf32(pa[it].x); u.y = to_tf32(pc[it].x);
                u.z = to_tf32(pa[it].y); u.w = to_tf32(pc[it].y);
                *(uint4*)&nb[r * YPS + 2 * jj] = u;
            }
        }
        __syncthreads();
    }

    // ---- S quad-reduce (over k4 lanes) ----
    #pragma unroll
    for (int mi = 0; mi < 2; mi++)
        #pragma unroll
        for (int h = 0; h < 2; h++) {
            Sp[mi][h] += __shfl_xor_sync(0xFFFFFFFFu, Sp[mi][h], 1);
            Sp[mi][h] += __shfl_xor_sync(0xFFFFFFFFu, Sp[mi][h], 2);
        }
    __syncthreads();                       // kt reads done -> alias as zst

    float* zst = sm + OFF_KT;              // [4 wn][64 m][32 d] = 8192 floats (fits)
    if (k4 == 0) {
        #pragma unroll
        for (int mi = 0; mi < 2; mi++) {
            sst[wn * 64 + mr + mi * 16 + g]     = Sp[mi][0];
            sst[wn * 64 + mr + mi * 16 + g + 8] = Sp[mi][1];
        }
    }
    #pragma unroll
    for (int mi = 0; mi < 2; mi++)
        #pragma unroll
        for (int di = 0; di < 4; di++) {
            int row = mr + mi * 16 + g;
            int d   = di * 8 + 2 * k4;
            float2 lo, hi;
            lo.x = z[mi][di][0]; lo.y = z[mi][di][1];
            hi.x = z[mi][di][2]; hi.y = z[mi][di][3];
            *(float2*)&zst[wn * 2048 + row * 32 + d]       = lo;
            *(float2*)&zst[wn * 2048 + (row + 8) * 32 + d] = hi;
        }
    __syncthreads();

    // ---- final: sum 4 wn slices, normalize, blend, store ----
    {
        const int m  = t & 63;
        const int d0 = (t >> 6) * 8;
        float Ssum = sst[m] + sst[64 + m] + sst[128 + m] + sst[192 + m];
        float inv = 0.5f / Ssum;
        #pragma unroll
        for (int dd = 0; dd < 8; dd++) {
            int d = d0 + dd;
            float zz = zst[m * 32 + d] + zst[2048 + m * 32 + d] +
                       zst[4096 + m * 32 + d] + zst[6144 + m * 32 + d];
            O[d * N_SZ + m0 + m] = zz * inv + 0.5f * Y[d * N_SZ + m0 + m];
        }
    }
}

extern "C" void kernel_launch(void* const* d_in, const int* in_sizes, int n_in,
                              void* d_out, int out_size) {
    const float* x = (const float*)d_in[0];
    float* out = (float*)d_out;
    cudaFuncSetAttribute(ms_iter_mma, cudaFuncAttributeMaxDynamicSharedMemorySize,
                         SMEM_BYTES);
    dim3 grid(N_SZ / BM, B_SZ);
    ms_iter_mma<<<grid, THREADS, SMEM_BYTES>>>(x, out, 0);   // x      -> g_ping
    ms_iter_mma<<<grid, THREADS, SMEM_BYTES>>>(x, out, 1);   // g_ping -> g_pong
    ms_iter_mma<<<grid, THREADS, SMEM_BYTES>>>(x, out, 2);   // g_pong -> out
}

// round 9
// speedup vs baseline: 1.5380x; 1.2995x over previous
#include <cuda_runtime.h>
#include <cuda_fp16.h>
#include <cstdint>

#define B_SZ 4
#define D_SZ 32
#define N_SZ 4096
#define BM 64                  // m-cols per CTA (2 CTAs/SM)
#define TN 128
#define NTILES (N_SZ / TN)
#define THREADS 256
#define YMS 68                 // ym tile stride (floats)
#define YPS 264                // fp32 paired yn row stride (floats)
#define Y16S 68                // fp16 yn tile stride in u32 words (64 pairs + 4 pad)

__device__ float g_ping[B_SZ * D_SZ * N_SZ];
__device__ float g_pong[B_SZ * D_SZ * N_SZ];

// smem 32-bit-word offsets
#define OFF_YM 0                            // [32][68] = 2176
#define OFF_YP 2176                         // 2 x [16][264] = 8448 (paired tf32 yn)
#define OFF_Y16 10624                       // 2 x [32][68] u32 = 4352 (fp16x2 yn)
#define OFF_SS 14976                        // [4][64]
#define SMEM_WORDS 15232
#define SMEM_BYTES (SMEM_WORDS * 4)         // 60928
#define OFF_ZST OFF_YP                      // zst aliases yp after the loop (8192<=8448)

static __device__ __forceinline__ uint32_t to_tf32(float f) {
    uint32_t r; asm("cvt.rna.tf32.f32 %0, %1;" : "=r"(r) : "f"(f)); return r;
}
static __device__ __forceinline__ float ex2a(float x) {
    float r; asm("ex2.approx.f32 %0, %1;" : "=f"(r) : "f"(x)); return r;
}
static __device__ __forceinline__ uint32_t packh2(float lo, float hi) {
    __half2 h = __floats2half2_rn(lo, hi);       // low = lo, high = hi
    return *reinterpret_cast<uint32_t*>(&h);
}
static __device__ __forceinline__ void mma8(float* c, const uint32_t* a,
                                            uint32_t b0, uint32_t b1) {
    asm("mma.sync.aligned.m16n8k8.row.col.f32.tf32.tf32.f32 "
        "{%0,%1,%2,%3},{%4,%5,%6,%7},{%8,%9},{%0,%1,%2,%3};"
        : "+f"(c[0]), "+f"(c[1]), "+f"(c[2]), "+f"(c[3])
        : "r"(a[0]), "r"(a[1]), "r"(a[2]), "r"(a[3]), "r"(b0), "r"(b1));
}
static __device__ __forceinline__ void mma16h(float* c, const uint32_t* a,
                                              uint32_t b0, uint32_t b1) {
    asm("mma.sync.aligned.m16n8k16.row.col.f32.f16.f16.f32 "
        "{%0,%1,%2,%3},{%4,%5,%6,%7},{%8,%9},{%0,%1,%2,%3};"
        : "+f"(c[0]), "+f"(c[1]), "+f"(c[2]), "+f"(c[3])
        : "r"(a[0]), "r"(a[1]), "r"(a[2]), "r"(a[3]), "r"(b0), "r"(b1));
}

// Mean-shift iteration. CTA owns 64 m-cols; warp (wm,wn) owns Kt rows
// [wm*32,+32) x cols [wn*32,+32) per 128-n tile. MMA1 (tf32) C-fragments are
// exp'ed and packed fp16x2 IN REGISTERS to become MMA2 (fp16 k16) A-fragments
// directly -- the C-frag ownership (rows g,8+g; cols 2k4,2k4+1) equals the
// m16n8k16 A-frag ownership. No Kt smem traffic at all.
__global__ __launch_bounds__(THREADS, 2)
void ms_iter_mma(const float* __restrict__ xin, float* __restrict__ xout, int mode) {
    extern __shared__ float sm[];
    float*    ym  = sm + OFF_YM;
    float*    ypb = sm + OFF_YP;
    uint32_t* y16 = reinterpret_cast<uint32_t*>(sm) + OFF_Y16;
    float*    sst = sm + OFF_SS;

    const float* gin  = (mode == 0) ? xin    : (mode == 1 ? g_ping : g_pong);
    float*       gout = (mode == 0) ? g_ping : (mode == 1 ? g_pong : xout);
    const int b  = blockIdx.y;
    const int m0 = blockIdx.x * BM;
    const float* Y = gin  + b * (D_SZ * N_SZ);
    float*       O = gout + b * (D_SZ * N_SZ);

    const int t    = threadIdx.x;
    const int lane = t & 31;
    const int wid  = t >> 5;
    const int g    = lane >> 2;
    const int k4   = lane & 3;
    const int wm   = wid & 1;
    const int wn   = wid >> 1;
    const int mr   = wm * 32;
    const int nc0  = wn * 32;

    // ---- stage Ym (tf32) [d][m], yp buf0 (tf32 paired), y16 buf0 (fp16x2) ----
    #pragma unroll
    for (int r = 0; r < 2; r++) {
        int v = t + r * THREADS;                 // 512 float4 = 64x32
        int d = v >> 4, j = (v & 15) * 4;
        float4 x = *(const float4*)&Y[d * N_SZ + m0 + j];
        uint4 u;
        u.x = to_tf32(x.x); u.y = to_tf32(x.y); u.z = to_tf32(x.z); u.w = to_tf32(x.w);
        *(uint4*)&ym[d * YMS + j] = u;
    }
    #pragma unroll
    for (int it = 0; it < 4; it++) {
        int v = t + it * THREADS;
        int r = v >> 6, jj = (v & 63) * 2;       // pair-row r, n-cols jj, jj+1
        int dlo = 8 * (r >> 2) + (r & 3);
        float2 a = *(const float2*)&Y[dlo * N_SZ + jj];
        float2 c = *(const float2*)&Y[(dlo + 4) * N_SZ + jj];
        uint4 u;
        u.x = to_tf32(a.x); u.y = to_tf32(c.x);
        u.z = to_tf32(a.y); u.w = to_tf32(c.y);
        *(uint4*)&ypb[r * YPS + 2 * jj] = u;
        y16[dlo * Y16S + (jj >> 1)]       = packh2(a.x, a.y);
        y16[(dlo + 4) * Y16S + (jj >> 1)] = packh2(c.x, c.y);
    }
    __syncthreads();

    // ---- hoist A1 frags (warp's 32 Ym rows, all 4 k-chunks) ----
    uint32_t a1[2][4][4];
    #pragma unroll
    for (int mi = 0; mi < 2; mi++)
        #pragma unroll
        for (int kc = 0; kc < 4; kc++) {
            int row = mr + mi * 16 + g;
            int d   = kc * 8 + k4;
            a1[mi][kc][0] = __float_as_uint(ym[d * YMS + row]);
            a1[mi][kc][1] = __float_as_uint(ym[d * YMS + row + 8]);
            a1[mi][kc][2] = __float_as_uint(ym[(d + 4) * YMS + row]);
            a1[mi][kc][3] = __float_as_uint(ym[(d + 4) * YMS + row + 8]);
        }

    float z[2][4][4];
    #pragma unroll
    for (int i = 0; i < 2; i++)
        #pragma unroll
        for (int j = 0; j < 4; j++)
            #pragma unroll
            for (int q = 0; q < 4; q++) z[i][j][q] = 0.0f;
    float Sp[2][2] = {{0.0f, 0.0f}, {0.0f, 0.0f}};
    const float C1 = 0.14426950408889634f;   // 0.1 * log2(e)

    for (int nt = 0; nt < NTILES; nt++) {
        float*    cur   = ypb + (nt & 1) * (16 * YPS);
        uint32_t* cur16 = y16 + (nt & 1) * (32 * Y16S);
        // ---- prefetch next yn pair-tile into regs ----
        float2 pa[4], pc[4];
        if (nt < NTILES - 1) {
            const int n1 = (nt + 1) * TN;
            #pragma unroll
            for (int it = 0; it < 4; it++) {
                int v = t + it * THREADS;
                int r = v >> 6, jj = (v & 63) * 2;
                int dlo = 8 * (r >> 2) + (r & 3);
                pa[it] = *(const float2*)&Y[dlo * N_SZ + n1 + jj];
                pc[it] = *(const float2*)&Y[(dlo + 4) * N_SZ + n1 + jj];
            }
        }

        // ---- per 16-col group: MMA1 x2 chunks -> exp+pack -> fp16 MMA2 ----
        #pragma unroll
        for (int nip = 0; nip < 2; nip++) {
            float c[2][2][4];                    // [ni][mi][q]
            #pragma unroll
            for (int i = 0; i < 2; i++)
                #pragma unroll
                for (int j = 0; j < 2; j++)
                    #pragma unroll
                    for (int q = 0; q < 4; q++) c[i][j][q] = 0.0f;
            #pragma unroll
            for (int ni = 0; ni < 2; ni++) {
                const int ncol = nc0 + nip * 16 + ni * 8 + g;
                #pragma unroll
                for (int kc = 0; kc < 4; kc++) {
                    float2 bv = *(const float2*)&cur[(4 * kc + k4) * YPS + 2 * ncol];
                    uint32_t b0 = __float_as_uint(bv.x);
                    uint32_t b1 = __float_as_uint(bv.y);
                    mma8(c[ni][0], a1[0][kc], b0, b1);
                    mma8(c[ni][1], a1[1][kc], b0, b1);
                }
            }
            // exp + pack: MMA1 C-frags become MMA2 A-frags in registers
            uint32_t af[2][4];                   // [mi][a0..a3]
            #pragma unroll
            for (int mi = 0; mi < 2; mi++) {
                float e00 = ex2a(c[0][mi][0] * C1), e01 = ex2a(c[0][mi][1] * C1);
                float e02 = ex2a(c[0][mi][2] * C1), e03 = ex2a(c[0][mi][3] * C1);
                float e10 = ex2a(c[1][mi][0] * C1), e11 = ex2a(c[1][mi][1] * C1);
                float e12 = ex2a(c[1][mi][2] * C1), e13 = ex2a(c[1][mi][3] * C1);
                Sp[mi][0] += (e00 + e01) + (e10 + e11);   // rows g
                Sp[mi][1] += (e02 + e03) + (e12 + e13);   // rows 8+g
                af[mi][0] = packh2(e00, e01);    // (g, 2k4),(g,2k4+1)   cols 0-7
                af[mi][1] = packh2(e02, e03);    // (8+g, ...)           cols 0-7
                af[mi][2] = packh2(e10, e11);    // (g, 8+2k4),...       cols 8-15
                af[mi][3] = packh2(e12, e13);    // (8+g, ...)           cols 8-15
            }
            // MMA2: k = these 16 n-cols; B = fp16 yn pairs (conflict-free LDS.32)
            const int pb = wn * 16 + nip * 8 + k4;
            #pragma unroll
            for (int di = 0; di < 4; di++) {
                uint32_t b0 = cur16[(8 * di + g) * Y16S + pb];
                uint32_t b1 = cur16[(8 * di + g) * Y16S + pb + 4];
                mma16h(z[0][di], af[0], b0, b1);
                mma16h(z[1][di], af[1], b0, b1);
            }
        }

        // ---- publish next buffers ----
        if (nt < NTILES - 1) {
            float*    nb   = ypb + ((nt + 1) & 1) * (16 * YPS);
            uint32_t* nb16 = y16 + ((nt + 1) & 1) * (32 * Y16S);
            #pragma unroll
            for (int it = 0; it < 4; it++) {
                int v = t + it * THREADS;
                int r = v >> 6, jj = (v & 63) * 2;
                int dlo = 8 * (r >> 2) + (r & 3);
                uint4 u;
                u.x = to_tf32(pa[it].x); u.y = to_tf32(pc[it].x);
                u.z = to_tf32(pa[it].y); u.w = to_tf32(pc[it].y);
                *(uint4*)&nb[r * YPS + 2 * jj] = u;
                nb16[dlo * Y16S + (jj >> 1)]       = packh2(pa[it].x, pa[it].y);
                nb16[(dlo + 4) * Y16S + (jj >> 1)] = packh2(pc[it].x, pc[it].y);
            }
        }
        __syncthreads();
    }

    // ---- S quad-reduce (over k4 lanes) ----
    #pragma unroll
    for (int mi = 0; mi < 2; mi++)
        #pragma unroll
        for (int h = 0; h < 2; h++) {
            Sp[mi][h] += __shfl_xor_sync(0xFFFFFFFFu, Sp[mi][h], 1);
            Sp[mi][h] += __shfl_xor_sync(0xFFFFFFFFu, Sp[mi][h], 2);
        }
    // loop-end __syncthreads() already ordered all smem reads -> alias yp as zst

    float* zst = sm + OFF_ZST;             // [4 wn][64 m][32 d] = 8192 floats
    if (k4 == 0) {
        #pragma unroll
        for (int mi = 0; mi < 2; mi++) {
            sst[wn * 64 + mr + mi * 16 + g]     = Sp[mi][0];
            sst[wn * 64 + mr + mi * 16 + g + 8] = Sp[mi][1];
        }
    }
    #pragma unroll
    for (int mi = 0; mi < 2; mi++)
        #pragma unroll
        for (int di = 0; di < 4; di++) {
            int row = mr + mi * 16 + g;
            int d   = di * 8 + 2 * k4;
            float2 lo, hi;
            lo.x = z[mi][di][0]; lo.y = z[mi][di][1];
            hi.x = z[mi][di][2]; hi.y = z[mi][di][3];
            *(float2*)&zst[wn * 2048 + row * 32 + d]       = lo;
            *(float2*)&zst[wn * 2048 + (row + 8) * 32 + d] = hi;
        }
    __syncthreads();

    // ---- final: sum 4 wn slices, normalize, blend, store ----
    {
        const int m  = t & 63;
        const int d0 = (t >> 6) * 8;
        float Ssum = sst[m] + sst[64 + m] + sst[128 + m] + sst[192 + m];
        float inv = 0.5f / Ssum;
        #pragma unroll
        for (int dd = 0; dd < 8; dd++) {
            int d = d0 + dd;
            float zz = zst[m * 32 + d] + zst[2048 + m * 32 + d] +
                       zst[4096 + m * 32 + d] + zst[6144 + m * 32 + d];
            O[d * N_SZ + m0 + m] = zz * inv + 0.5f * Y[d * N_SZ + m0 + m];
        }
    }
}

extern "C" void kernel_launch(void* const* d_in, const int* in_sizes, int n_in,
                              void* d_out, int out_size) {
    const float* x = (const float*)d_in[0];
    float* out = (float*)d_out;
    cudaFuncSetAttribute(ms_iter_mma, cudaFuncAttributeMaxDynamicSharedMemorySize,
                         SMEM_BYTES);
    dim3 grid(N_SZ / BM, B_SZ);
    ms_iter_mma<<<grid, THREADS, SMEM_BYTES>>>(x, out, 0);   // x      -> g_ping
    ms_iter_mma<<<grid, THREADS, SMEM_BYTES>>>(x, out, 1);   // g_ping -> g_pong
    ms_iter_mma<<<grid, THREADS, SMEM_BYTES>>>(x, out, 2);   // g_pong -> out
}

// round 10
// speedup vs baseline: 2.0473x; 1.3312x over previous
#include <cuda_runtime.h>
#include <cuda_fp16.h>
#include <cstdint>

#define B_SZ 4
#define D_SZ 32
#define N_SZ 4096
#define BM 64                  // m-cols per CTA (2 CTAs/SM)
#define TN 128
#define NTILES (N_SZ / TN)
#define THREADS 256
#define YMQS 68                // ymq stride (u32)
#define YQS 132                // yqd row stride (uint2 units)
#define Y16S 68                // y16n stride (u32)

__device__ float g_ping[B_SZ * D_SZ * N_SZ];
__device__ float g_pong[B_SZ * D_SZ * N_SZ];

// smem u32-word offsets
#define OFF_YMQ 0                           // [16][68] = 1088 (fp16x2 Ym, d-paired)
#define OFF_YQD 1088                        // 2 x [8][132] uint2 = 4224 u32 (MMA1 B)
#define OFF_Y16N 5312                       // 2 x [32][68] u32 = 4352 (MMA2 B, n-paired)
#define OFF_SS 9664                         // [4][64]
#define SMEM_WORDS 9920
#define SMEM_BYTES (SMEM_WORDS * 4)         // 39680
#define OFF_ZST OFF_YQD                     // zst aliases yqd+y16n (8576 >= 8192)

static __device__ __forceinline__ float ex2a(float x) {
    float r; asm("ex2.approx.f32 %0, %1;" : "=f"(r) : "f"(x)); return r;
}
static __device__ __forceinline__ uint32_t packh2(float lo, float hi) {
    __half2 h = __floats2half2_rn(lo, hi);       // low = lo, high = hi
    return *reinterpret_cast<uint32_t*>(&h);
}
static __device__ __forceinline__ void mma16h(float* c, const uint32_t* a,
                                              uint32_t b0, uint32_t b1) {
    asm("mma.sync.aligned.m16n8k16.row.col.f32.f16.f16.f32 "
        "{%0,%1,%2,%3},{%4,%5,%6,%7},{%8,%9},{%0,%1,%2,%3};"
        : "+f"(c[0]), "+f"(c[1]), "+f"(c[2]), "+f"(c[3])
        : "r"(a[0]), "r"(a[1]), "r"(a[2]), "r"(a[3]), "r"(b0), "r"(b1));
}

// Mean-shift iteration, all-fp16 tensor path (fp16 mantissa == tf32 mantissa).
// CTA owns 64 m-cols; warp (wm,wn) owns Kt rows [wm*32,+32) x cols [wn*32,+32).
// MMA1 (fp16 k16) C-frags are exp'ed + packed fp16x2 in registers to become the
// MMA2 (fp16 k16) A-frags directly: Kt never touches smem.
__global__ __launch_bounds__(THREADS, 2)
void ms_iter_mma(const float* __restrict__ xin, float* __restrict__ xout, int mode) {
    extern __shared__ float sm[];
    uint32_t* ymq  = reinterpret_cast<uint32_t*>(sm) + OFF_YMQ;
    uint2*    yqd  = reinterpret_cast<uint2*>(reinterpret_cast<uint32_t*>(sm) + OFF_YQD);
    uint32_t* y16n = reinterpret_cast<uint32_t*>(sm) + OFF_Y16N;
    float*    sst  = sm + OFF_SS;

    const float* gin  = (mode == 0) ? xin    : (mode == 1 ? g_ping : g_pong);
    float*       gout = (mode == 0) ? g_ping : (mode == 1 ? g_pong : xout);
    const int b  = blockIdx.y;
    const int m0 = blockIdx.x * BM;
    const float* Y = gin  + b * (D_SZ * N_SZ);
    float*       O = gout + b * (D_SZ * N_SZ);

    const int t    = threadIdx.x;
    const int lane = t & 31;
    const int wid  = t >> 5;
    const int g    = lane >> 2;
    const int k4   = lane & 3;
    const int wm   = wid & 1;
    const int wn   = wid >> 1;
    const int mr   = wm * 32;
    const int nc0  = wn * 32;

    // ---- stage ymq: [dpair r][m] = pack(Y[2r][m], Y[2r+1][m]) ----
    #pragma unroll
    for (int r2 = 0; r2 < 2; r2++) {
        int v = t + r2 * THREADS;                // 512 items
        int r = v >> 5, mm = (v & 31) * 2;
        float2 x0 = *(const float2*)&Y[(2 * r) * N_SZ + m0 + mm];
        float2 x1 = *(const float2*)&Y[(2 * r + 1) * N_SZ + m0 + mm];
        ymq[r * YMQS + mm]     = packh2(x0.x, x1.x);
        ymq[r * YMQS + mm + 1] = packh2(x0.y, x1.y);
    }
    // ---- stage yn buf0: yqd (MMA1 B, d-paired) + y16n (MMA2 B, n-paired) ----
    #pragma unroll
    for (int it = 0; it < 2; it++) {
        int v = t + it * THREADS;                // 512 items
        int q = v >> 6, nn = (v & 63) * 2;       // q: 4kc+k4 row; nn: n-col pair
        int d0 = 16 * (q >> 2) + 2 * (q & 3);
        float2 r0 = *(const float2*)&Y[d0 * N_SZ + nn];
        float2 r1 = *(const float2*)&Y[(d0 + 1) * N_SZ + nn];
        float2 r8 = *(const float2*)&Y[(d0 + 8) * N_SZ + nn];
        float2 r9 = *(const float2*)&Y[(d0 + 9) * N_SZ + nn];
        yqd[q * YQS + nn]     = make_uint2(packh2(r0.x, r1.x), packh2(r8.x, r9.x));
        yqd[q * YQS + nn + 1] = make_uint2(packh2(r0.y, r1.y), packh2(r8.y, r9.y));
        int np = nn >> 1;
        y16n[d0 * Y16S + np]       = packh2(r0.x, r0.y);
        y16n[(d0 + 1) * Y16S + np] = packh2(r1.x, r1.y);
        y16n[(d0 + 8) * Y16S + np] = packh2(r8.x, r8.y);
        y16n[(d0 + 9) * Y16S + np] = packh2(r9.x, r9.y);
    }
    __syncthreads();

    // ---- hoist A1 frags (fp16): warp's 32 Ym rows, 2 k16 chunks ----
    uint32_t a1h[2][2][4];                       // [mi][kc][frag]
    #pragma unroll
    for (int mi = 0; mi < 2; mi++)
        #pragma unroll
        for (int kc = 0; kc < 2; kc++) {
            int row = mr + mi * 16 + g;
            a1h[mi][kc][0] = ymq[(8 * kc + k4) * YMQS + row];
            a1h[mi][kc][1] = ymq[(8 * kc + k4) * YMQS + row + 8];
            a1h[mi][kc][2] = ymq[(8 * kc + 4 + k4) * YMQS + row];
            a1h[mi][kc][3] = ymq[(8 * kc + 4 + k4) * YMQS + row + 8];
        }

    float z[2][4][4];
    #pragma unroll
    for (int i = 0; i < 2; i++)
        #pragma unroll
        for (int j = 0; j < 4; j++)
            #pragma unroll
            for (int q = 0; q < 4; q++) z[i][j][q] = 0.0f;
    float Sp[2][2] = {{0.0f, 0.0f}, {0.0f, 0.0f}};
    const float C1 = 0.14426950408889634f;   // 0.1 * log2(e)

    for (int nt = 0; nt < NTILES; nt++) {
        uint2*    curq  = yqd  + (nt & 1) * (8 * YQS);
        uint32_t* cur16 = y16n + (nt & 1) * (32 * Y16S);
        // ---- prefetch next yn tile into regs ----
        float2 pr[2][4];
        if (nt < NTILES - 1) {
            const int n1 = (nt + 1) * TN;
            #pragma unroll
            for (int it = 0; it < 2; it++) {
                int v = t + it * THREADS;
                int q = v >> 6, nn = (v & 63) * 2;
                int d0 = 16 * (q >> 2) + 2 * (q & 3);
                pr[it][0] = *(const float2*)&Y[d0 * N_SZ + n1 + nn];
                pr[it][1] = *(const float2*)&Y[(d0 + 1) * N_SZ + n1 + nn];
                pr[it][2] = *(const float2*)&Y[(d0 + 8) * N_SZ + n1 + nn];
                pr[it][3] = *(const float2*)&Y[(d0 + 9) * N_SZ + n1 + nn];
            }
        }

        // ---- per 16-col group: fp16 MMA1 x2 -> exp+pack -> fp16 MMA2 ----
        #pragma unroll
        for (int nip = 0; nip < 2; nip++) {
            float c[2][2][4];                    // [ni][mi][q]
            #pragma unroll
            for (int i = 0; i < 2; i++)
                #pragma unroll
                for (int j = 0; j < 2; j++)
                    #pragma unroll
                    for (int q = 0; q < 4; q++) c[i][j][q] = 0.0f;
            #pragma unroll
            for (int ni = 0; ni < 2; ni++) {
                const int ncol = nc0 + nip * 16 + ni * 8 + g;
                #pragma unroll
                for (int kc = 0; kc < 2; kc++) {
                    uint2 bv = curq[(4 * kc + k4) * YQS + ncol];
                    mma16h(c[ni][0], a1h[0][kc], bv.x, bv.y);
                    mma16h(c[ni][1], a1h[1][kc], bv.x, bv.y);
                }
            }
            // exp + pack: MMA1 C-frags -> MMA2 A-frags in registers
            uint32_t af[2][4];
            #pragma unroll
            for (int mi = 0; mi < 2; mi++) {
                float e00 = ex2a(c[0][mi][0] * C1), e01 = ex2a(c[0][mi][1] * C1);
                float e02 = ex2a(c[0][mi][2] * C1), e03 = ex2a(c[0][mi][3] * C1);
                float e10 = ex2a(c[1][mi][0] * C1), e11 = ex2a(c[1][mi][1] * C1);
                float e12 = ex2a(c[1][mi][2] * C1), e13 = ex2a(c[1][mi][3] * C1);
                Sp[mi][0] += (e00 + e01) + (e10 + e11);   // rows g
                Sp[mi][1] += (e02 + e03) + (e12 + e13);   // rows 8+g
                af[mi][0] = packh2(e00, e01);
                af[mi][1] = packh2(e02, e03);
                af[mi][2] = packh2(e10, e11);
                af[mi][3] = packh2(e12, e13);
            }
            // MMA2: k = these 16 n-cols; B = fp16 n-paired yn (conflict-free)
            const int pb = wn * 16 + nip * 8 + k4;
            #pragma unroll
            for (int di = 0; di < 4; di++) {
                uint32_t b0 = cur16[(8 * di + g) * Y16S + pb];
                uint32_t b1 = cur16[(8 * di + g) * Y16S + pb + 4];
                mma16h(z[0][di], af[0], b0, b1);
                mma16h(z[1][di], af[1], b0, b1);
            }
        }

        // ---- publish next buffers ----
        if (nt < NTILES - 1) {
            uint2*    nbq  = yqd  + ((nt + 1) & 1) * (8 * YQS);
            uint32_t* nb16 = y16n + ((nt + 1) & 1) * (32 * Y16S);
            #pragma unroll
            for (int it = 0; it < 2; it++) {
                int v = t + it * THREADS;
                int q = v >> 6, nn = (v & 63) * 2;
                int d0 = 16 * (q >> 2) + 2 * (q & 3);
                float2 r0 = pr[it][0], r1 = pr[it][1], r8 = pr[it][2], r9 = pr[it][3];
                nbq[q * YQS + nn]     = make_uint2(packh2(r0.x, r1.x), packh2(r8.x, r9.x));
                nbq[q * YQS + nn + 1] = make_uint2(packh2(r0.y, r1.y), packh2(r8.y, r9.y));
                int np = nn >> 1;
                nb16[d0 * Y16S + np]       = packh2(r0.x, r0.y);
                nb16[(d0 + 1) * Y16S + np] = packh2(r1.x, r1.y);
                nb16[(d0 + 8) * Y16S + np] = packh2(r8.x, r8.y);
                nb16[(d0 + 9) * Y16S + np] = packh2(r9.x, r9.y);
            }
        }
        __syncthreads();
    }

    // ---- S quad-reduce (over k4 lanes) ----
    #pragma unroll
    for (int mi = 0; mi < 2; mi++)
        #pragma unroll
        for (int h = 0; h < 2; h++) {
            Sp[mi][h] += __shfl_xor_sync(0xFFFFFFFFu, Sp[mi][h], 1);
            Sp[mi][h] += __shfl_xor_sync(0xFFFFFFFFu, Sp[mi][h], 2);
        }
    // loop-end __syncthreads() already ordered all smem reads -> alias as zst

    float* zst = sm + OFF_ZST;             // [4 wn][64 m][32 d] = 8192 floats
    if (k4 == 0) {
        #pragma unroll
        for (int mi = 0; mi < 2; mi++) {
            sst[wn * 64 + mr + mi * 16 + g]     = Sp[mi][0];
            sst[wn * 64 + mr + mi * 16 + g + 8] = Sp[mi][1];
        }
    }
    #pragma unroll
    for (int mi = 0; mi < 2; mi++)
        #pragma unroll
        for (int di = 0; di < 4; di++) {
            int row = mr + mi * 16 + g;
            int d   = di * 8 + 2 * k4;
            float2 lo, hi;
            lo.x = z[mi][di][0]; lo.y = z[mi][di][1];
            hi.x = z[mi][di][2]; hi.y = z[mi][di][3];
            *(float2*)&zst[wn * 2048 + row * 32 + d]       = lo;
            *(float2*)&zst[wn * 2048 + (row + 8) * 32 + d] = hi;
        }
    __syncthreads();

    // ---- final: sum 4 wn slices, normalize, blend, store ----
    {
        const int m  = t & 63;
        const int d0 = (t >> 6) * 8;
        float Ssum = sst[m] + sst[64 + m] + sst[128 + m] + sst[192 + m];
        float inv = 0.5f / Ssum;
        #pragma unroll
        for (int dd = 0; dd < 8; dd++) {
            int d = d0 + dd;
            float zz = zst[m * 32 + d] + zst[2048 + m * 32 + d] +
                       zst[4096 + m * 32 + d] + zst[6144 + m * 32 + d];
            O[d * N_SZ + m0 + m] = zz * inv + 0.5f * Y[d * N_SZ + m0 + m];
        }
    }
}

extern "C" void kernel_launch(void* const* d_in, const int* in_sizes, int n_in,
                              void* d_out, int out_size) {
    const float* x = (const float*)d_in[0];
    float* out = (float*)d_out;
    cudaFuncSetAttribute(ms_iter_mma, cudaFuncAttributeMaxDynamicSharedMemorySize,
                         SMEM_BYTES);
    dim3 grid(N_SZ / BM, B_SZ);
    ms_iter_mma<<<grid, THREADS, SMEM_BYTES>>>(x, out, 0);   // x      -> g_ping
    ms_iter_mma<<<grid, THREADS, SMEM_BYTES>>>(x, out, 1);   // g_ping -> g_pong
    ms_iter_mma<<<grid, THREADS, SMEM_BYTES>>>(x, out, 2);   // g_pong -> out
}

// round 11
// speedup vs baseline: 2.1384x; 1.0445x over previous
#include <cuda_runtime.h>
#include <cuda_fp16.h>
#include <cstdint>

#define B_SZ 4
#define D_SZ 32
#define N_SZ 4096
#define BM 64                  // m-cols per CTA (2 CTAs/SM)
#define TN 128
#define NTILES (N_SZ / TN)
#define THREADS 256
#define YMQS 68                // ymq stride (u32)
#define Y16S 68                // y16n stride (u32); row stride 272B -> LDSM conflict-free

__device__ float g_ping[B_SZ * D_SZ * N_SZ];
__device__ float g_pong[B_SZ * D_SZ * N_SZ];

// smem u32-word offsets
#define OFF_YMQ 0                           // [16][68] = 1088 (fp16x2 C1*Ym, d-paired)
#define OFF_Y16N 1088                       // 2 x [32][68] = 4352 (fp16x2 yn, n-paired)
#define OFF_SS 8192                         // [4][64] (after zst region)
#define SMEM_WORDS 8448
#define SMEM_BYTES (SMEM_WORDS * 4)         // 33792
// zst aliases words 0..8191 post-loop

static __device__ __forceinline__ uint32_t smem_u32(const void* p) {
    uint32_t a;
    asm("{ .reg .u64 t; cvta.to.shared.u64 t, %1; cvt.u32.u64 %0, t; }" : "=r"(a) : "l"(p));
    return a;
}
static __device__ __forceinline__ float ex2a(float x) {
    float r; asm("ex2.approx.f32 %0, %1;" : "=f"(r) : "f"(x)); return r;
}
static __device__ __forceinline__ uint32_t packh2(float lo, float hi) {
    __half2 h = __floats2half2_rn(lo, hi);
    return *reinterpret_cast<uint32_t*>(&h);
}
static __device__ __forceinline__ void ldsm_x4(uint32_t* r, uint32_t addr) {
    asm volatile("ldmatrix.sync.aligned.m8n8.x4.shared.b16 {%0,%1,%2,%3}, [%4];"
        : "=r"(r[0]), "=r"(r[1]), "=r"(r[2]), "=r"(r[3]) : "r"(addr));
}
static __device__ __forceinline__ void ldsm_x4_t(uint32_t* r, uint32_t addr) {
    asm volatile("ldmatrix.sync.aligned.m8n8.x4.trans.shared.b16 {%0,%1,%2,%3}, [%4];"
        : "=r"(r[0]), "=r"(r[1]), "=r"(r[2]), "=r"(r[3]) : "r"(addr));
}
static __device__ __forceinline__ void mma16h(float* c, const uint32_t* a,
                                              uint32_t b0, uint32_t b1) {
    asm("mma.sync.aligned.m16n8k16.row.col.f32.f16.f16.f32 "
        "{%0,%1,%2,%3},{%4,%5,%6,%7},{%8,%9},{%0,%1,%2,%3};"
        : "+f"(c[0]), "+f"(c[1]), "+f"(c[2]), "+f"(c[3])
        : "r"(a[0]), "r"(a[1]), "r"(a[2]), "r"(a[3]), "r"(b0), "r"(b1));
}

// Mean-shift iteration, all-fp16 tensor path. Kt stays in registers
// (MMA1 C-frag == MMA2 A-frag layout). C1=0.1*log2(e) is folded into the
// staged Ym operand so exp is a bare ex2 on the accumulator. All B-frags
// come from ONE [d][n] fp16 tile via ldmatrix(.trans).
__global__ __launch_bounds__(THREADS, 2)
void ms_iter_mma(const float* __restrict__ xin, float* __restrict__ xout, int mode) {
    extern __shared__ float sm[];
    uint32_t* smw  = reinterpret_cast<uint32_t*>(sm);
    uint32_t* ymq  = smw + OFF_YMQ;
    uint32_t* y16n = smw + OFF_Y16N;
    float*    sst  = sm + OFF_SS;

    const float* gin  = (mode == 0) ? xin    : (mode == 1 ? g_ping : g_pong);
    float*       gout = (mode == 0) ? g_ping : (mode == 1 ? g_pong : xout);
    const int b  = blockIdx.y;
    const int m0 = blockIdx.x * BM;
    const float* Y = gin  + b * (D_SZ * N_SZ);
    float*       O = gout + b * (D_SZ * N_SZ);

    const int t    = threadIdx.x;
    const int lane = t & 31;
    const int wid  = t >> 5;
    const int g    = lane >> 2;
    const int k4   = lane & 3;
    const int wm   = wid & 1;
    const int wn   = wid >> 1;
    const int mr   = wm * 32;
    const float C1 = 0.14426950408889634f;   // 0.1 * log2(e)

    // ldmatrix per-lane base addresses (bytes)
    const int mat = lane >> 3, rr = lane & 7;
    const uint32_t y16b = smem_u32(sm) + OFF_Y16N * 4;
    // MMA1 (.trans): mat = {kc-half(lo/hi d-octet) , ni}  -> regs {b0,b1}x{ni0,ni1}
    const uint32_t a1base = y16b + (uint32_t)((((mat & 1) * 8 + rr) * Y16S
                                               + 16 * wn + (mat >> 1) * 4) * 4);
    // MMA2 (non-trans): mat = {di-pair half, b0/b1}      -> regs {b0,b1}x{di0,di1}
    const uint32_t a2base = y16b + (uint32_t)((((mat >> 1) * 8 + rr) * Y16S
                                               + 16 * wn + (mat & 1) * 4) * 4);

    // staging ids: thread covers row sd, 16 pixels at sc
    const int sd = t >> 3;
    const int sc = (t & 7) * 16;

    // ---- stage ymq: [dpair r][m] = pack(C1*Y[2r][m], C1*Y[2r+1][m]) ----
    #pragma unroll
    for (int r2 = 0; r2 < 2; r2++) {
        int v = t + r2 * THREADS;                // 512 items
        int r = v >> 5, mm = (v & 31) * 2;
        float2 x0 = *(const float2*)&Y[(2 * r) * N_SZ + m0 + mm];
        float2 x1 = *(const float2*)&Y[(2 * r + 1) * N_SZ + m0 + mm];
        ymq[r * YMQS + mm]     = packh2(C1 * x0.x, C1 * x1.x);
        ymq[r * YMQS + mm + 1] = packh2(C1 * x0.y, C1 * x1.y);
    }
    // ---- stage y16n buf0: row sd, pixels sc..sc+15 ----
    {
        float4 q0 = *(const float4*)&Y[sd * N_SZ + sc];
        float4 q1 = *(const float4*)&Y[sd * N_SZ + sc + 4];
        float4 q2 = *(const float4*)&Y[sd * N_SZ + sc + 8];
        float4 q3 = *(const float4*)&Y[sd * N_SZ + sc + 12];
        uint32_t* dst = y16n + sd * Y16S + (sc >> 1);
        uint4 u0 = make_uint4(packh2(q0.x, q0.y), packh2(q0.z, q0.w),
                              packh2(q1.x, q1.y), packh2(q1.z, q1.w));
        uint4 u1 = make_uint4(packh2(q2.x, q2.y), packh2(q2.z, q2.w),
                              packh2(q3.x, q3.y), packh2(q3.z, q3.w));
        *(uint4*)&dst[0] = u0;
        *(uint4*)&dst[4] = u1;
    }
    __syncthreads();

    // ---- hoist A1 frags (fp16, pre-scaled by C1): 32 Ym rows, 2 k16 chunks ----
    uint32_t a1h[2][2][4];
    #pragma unroll
    for (int mi = 0; mi < 2; mi++)
        #pragma unroll
        for (int kc = 0; kc < 2; kc++) {
            int row = mr + mi * 16 + g;
            a1h[mi][kc][0] = ymq[(8 * kc + k4) * YMQS + row];
            a1h[mi][kc][1] = ymq[(8 * kc + k4) * YMQS + row + 8];
            a1h[mi][kc][2] = ymq[(8 * kc + 4 + k4) * YMQS + row];
            a1h[mi][kc][3] = ymq[(8 * kc + 4 + k4) * YMQS + row + 8];
        }

    float z[2][4][4];
    #pragma unroll
    for (int i = 0; i < 2; i++)
        #pragma unroll
        for (int j = 0; j < 4; j++)
            #pragma unroll
            for (int q = 0; q < 4; q++) z[i][j][q] = 0.0f;
    float Sp[2][2] = {{0.0f, 0.0f}, {0.0f, 0.0f}};

    for (int nt = 0; nt < NTILES; nt++) {
        const uint32_t bufoff = (uint32_t)(nt & 1) * (32 * Y16S * 4);
        // ---- prefetch next yn tile into regs ----
        float4 pr[4];
        if (nt < NTILES - 1) {
            const int n1 = (nt + 1) * TN;
            pr[0] = *(const float4*)&Y[sd * N_SZ + n1 + sc];
            pr[1] = *(const float4*)&Y[sd * N_SZ + n1 + sc + 4];
            pr[2] = *(const float4*)&Y[sd * N_SZ + n1 + sc + 8];
            pr[3] = *(const float4*)&Y[sd * N_SZ + n1 + sc + 12];
        }

        // ---- per 16-col group: MMA1 -> ex2+pack -> MMA2, Kt in registers ----
        #pragma unroll
        for (int nip = 0; nip < 2; nip++) {
            float c[2][2][4];                    // [ni][mi][q]
            #pragma unroll
            for (int i = 0; i < 2; i++)
                #pragma unroll
                for (int j = 0; j < 2; j++)
                    #pragma unroll
                    for (int q = 0; q < 4; q++) c[i][j][q] = 0.0f;
            uint32_t bq0[4], bq1[4];
            ldsm_x4_t(bq0, a1base + bufoff + (uint32_t)(nip * 32));
            ldsm_x4_t(bq1, a1base + bufoff + (uint32_t)(16 * Y16S * 4 + nip * 32));
            mma16h(c[0][0], a1h[0][0], bq0[0], bq0[1]);
            mma16h(c[0][1], a1h[1][0], bq0[0], bq0[1]);
            mma16h(c[1][0], a1h[0][0], bq0[2], bq0[3]);
            mma16h(c[1][1], a1h[1][0], bq0[2], bq0[3]);
            mma16h(c[0][0], a1h[0][1], bq1[0], bq1[1]);
            mma16h(c[0][1], a1h[1][1], bq1[0], bq1[1]);
            mma16h(c[1][0], a1h[0][1], bq1[2], bq1[3]);
            mma16h(c[1][1], a1h[1][1], bq1[2], bq1[3]);

            // ex2 + pack: MMA1 C-frags -> MMA2 A-frags in registers
            uint32_t af[2][4];
            #pragma unroll
            for (int mi = 0; mi < 2; mi++) {
                float e00 = ex2a(c[0][mi][0]), e01 = ex2a(c[0][mi][1]);
                float e02 = ex2a(c[0][mi][2]), e03 = ex2a(c[0][mi][3]);
                float e10 = ex2a(c[1][mi][0]), e11 = ex2a(c[1][mi][1]);
                float e12 = ex2a(c[1][mi][2]), e13 = ex2a(c[1][mi][3]);
                Sp[mi][0] += (e00 + e01) + (e10 + e11);   // rows g
                Sp[mi][1] += (e02 + e03) + (e12 + e13);   // rows 8+g
                af[mi][0] = packh2(e00, e01);
                af[mi][1] = packh2(e02, e03);
                af[mi][2] = packh2(e10, e11);
                af[mi][3] = packh2(e12, e13);
            }
            // MMA2: k = these 16 n-cols; B-frags via non-trans ldmatrix
            uint32_t b2a[4], b2b[4];
            ldsm_x4(b2a, a2base + bufoff + (uint32_t)(nip * 32));
            ldsm_x4(b2b, a2base + bufoff + (uint32_t)(16 * Y16S * 4 + nip * 32));
            mma16h(z[0][0], af[0], b2a[0], b2a[1]);
            mma16h(z[1][0], af[1], b2a[0], b2a[1]);
            mma16h(z[0][1], af[0], b2a[2], b2a[3]);
            mma16h(z[1][1], af[1], b2a[2], b2a[3]);
            mma16h(z[0][2], af[0], b2b[0], b2b[1]);
            mma16h(z[1][2], af[1], b2b[0], b2b[1]);
            mma16h(z[0][3], af[0], b2b[2], b2b[3]);
            mma16h(z[1][3], af[1], b2b[2], b2b[3]);
        }

        // ---- publish next buffer ----
        if (nt < NTILES - 1) {
            uint32_t* nb = y16n + ((nt + 1) & 1) * (32 * Y16S);
            uint32_t* dst = nb + sd * Y16S + (sc >> 1);
            uint4 u0 = make_uint4(packh2(pr[0].x, pr[0].y), packh2(pr[0].z, pr[0].w),
                                  packh2(pr[1].x, pr[1].y), packh2(pr[1].z, pr[1].w));
            uint4 u1 = make_uint4(packh2(pr[2].x, pr[2].y), packh2(pr[2].z, pr[2].w),
                                  packh2(pr[3].x, pr[3].y), packh2(pr[3].z, pr[3].w));
            *(uint4*)&dst[0] = u0;
            *(uint4*)&dst[4] = u1;
        }
        __syncthreads();
    }

    // ---- S quad-reduce (over k4 lanes) ----
    #pragma unroll
    for (int mi = 0; mi < 2; mi++)
        #pragma unroll
        for (int h = 0; h < 2; h++) {
            Sp[mi][h] += __shfl_xor_sync(0xFFFFFFFFu, Sp[mi][h], 1);
            Sp[mi][h] += __shfl_xor_sync(0xFFFFFFFFu, Sp[mi][h], 2);
        }
    // loop-end __syncthreads() ordered all smem reads -> alias words 0.. as zst

    float* zst = sm;                       // [4 wn][64 m][32 d] = 8192 floats
    if (k4 == 0) {
        #pragma unroll
        for (int mi = 0; mi < 2; mi++) {
            sst[wn * 64 + mr + mi * 16 + g]     = Sp[mi][0];
            sst[wn * 64 + mr + mi * 16 + g + 8] = Sp[mi][1];
        }
    }
    #pragma unroll
    for (int mi = 0; mi < 2; mi++)
        #pragma unroll
        for (int di = 0; di < 4; di++) {
            int row = mr + mi * 16 + g;
            int d   = di * 8 + 2 * k4;
            float2 lo, hi;
            lo.x = z[mi][di][0]; lo.y = z[mi][di][1];
            hi.x = z[mi][di][2]; hi.y = z[mi][di][3];
            *(float2*)&zst[wn * 2048 + row * 32 + d]       = lo;
            *(float2*)&zst[wn * 2048 + (row + 8) * 32 + d] = hi;
        }
    __syncthreads();

    // ---- final: sum 4 wn slices, normalize, blend, store ----
    {
        const int m  = t & 63;
        const int d0 = (t >> 6) * 8;
        float Ssum = sst[m] + sst[64 + m] + sst[128 + m] + sst[192 + m];
        float inv = 0.5f / Ssum;
        #pragma unroll
        for (int dd = 0; dd < 8; dd++) {
            int d = d0 + dd;
            float zz = zst[m * 32 + d] + zst[2048 + m * 32 + d] +
                       zst[4096 + m * 32 + d] + zst[6144 + m * 32 + d];
            O[d * N_SZ + m0 + m] = zz * inv + 0.5f * Y[d * N_SZ + m0 + m];
        }
    }
}

extern "C" void kernel_launch(void* const* d_in, const int* in_sizes, int n_in,
                              void* d_out, int out_size) {
    const float* x = (const float*)d_in[0];
    float* out = (float*)d_out;
    cudaFuncSetAttribute(ms_iter_mma, cudaFuncAttributeMaxDynamicSharedMemorySize,
                         SMEM_BYTES);
    dim3 grid(N_SZ / BM, B_SZ);
    ms_iter_mma<<<grid, THREADS, SMEM_BYTES>>>(x, out, 0);   // x      -> g_ping
    ms_iter_mma<<<grid, THREADS, SMEM_BYTES>>>(x, out, 1);   // g_ping -> g_pong
    ms_iter_mma<<<grid, THREADS, SMEM_BYTES>>>(x, out, 2);   // g_pong -> out
}